// round 12
// baseline (speedup 1.0000x reference)
#include <cuda_runtime.h>
#include <cstdint>

#define Nn 8192
#define Mm 512

// ---------------- device scratch (static .bss; allocation-free) ----------------
__device__ float g_px[(size_t)(Nn + 1) * 2560];   // childsum x-proj; row Nn stays 0 (sentinel)
__device__ float g_qx[(size_t)Nn * 2560];         // chain x-proj
__device__ float g_acch[(size_t)(Nn + 1) * Mm];
__device__ float g_accfc[(size_t)(Nn + 1) * Mm];
__device__ float g_acczc[(size_t)(Nn + 1) * Mm];
__device__ float g_csc[(size_t)Nn * Mm];
__device__ float g_csh[(size_t)Nn * Mm];
__device__ float g_chc[(size_t)(Nn + 1) * Mm];    // row Nn stays 0 forever (root's phantom)
__device__ float g_chh[(size_t)(Nn + 1) * Mm];    // row Nn stays 0 forever
__device__ float g_chs[(size_t)Nn * Mm];
__device__ float g_chig[(size_t)Nn * Mm];
__device__ float g_chog[(size_t)Nn * Mm];
__device__ float g_chfc[(size_t)Nn * Mm];

// pre-built weight tile images (tf32, k-permuted, gate-interleaved, 36-stride)
// unit = one 128-col x 32-k chunk image = 4608 floats
#define UB_CHWH  0      // 16 tiles x 16 chunks  (chain Wh, (i,o,f,z)/j interleave)
#define UB_CSIOW 256    // 16 tiles x 32 chunks  (childsum [Wio|Wum] fused, (i,o,w,pad)/j)
#define UB_CHWUM 768    // 4  tiles x 16         (chain Wum, natural)
#define UB_CSFZ  832    // 8  tiles x 16         (childsum Wfz, (f,z)/j)
#define UB_CSWX  960    // 20 tiles x 16         (childsum Wx, natural)
#define UB_CHWX  1280   // 20 tiles x 16         (chain Wx, natural)
#define UNITS_TOTAL 1600
__device__ __align__(16) float g_wt[(size_t)UNITS_TOTAL * 4608];

__device__ float g_bias_chwh[2048];
__device__ float g_bias_csiow[2048];
__device__ float g_bias_csfz[1024];

__device__ int g_parent[Nn];
__device__ int g_depth[Nn];
__device__ int g_order[Nn];
__device__ int g_parorder[Nn];
__device__ int g_lvlstart[256];
__device__ int g_lvlcnt[256];
__device__ int g_maxdepth;

__device__ unsigned g_barcnt;
__device__ unsigned g_bargen;

// ---------------- helpers ----------------
__device__ __forceinline__ float sigf(float x) { return 1.f / (1.f + __expf(-x)); }

__device__ __forceinline__ float to_tf32(float x) {
    float r;
    asm("cvt.rna.tf32.f32 %0, %1;" : "=f"(r) : "f"(x));
    return r;
}

__device__ __forceinline__ void mma8(float* c, unsigned a0, unsigned a1, unsigned a2,
                                     unsigned a3, unsigned b0, unsigned b1) {
    asm("mma.sync.aligned.m16n8k8.row.col.f32.tf32.tf32.f32 "
        "{%0,%1,%2,%3}, {%4,%5,%6,%7}, {%8,%9}, {%0,%1,%2,%3};"
        : "+f"(c[0]), "+f"(c[1]), "+f"(c[2]), "+f"(c[3])
        : "r"(a0), "r"(a1), "r"(a2), "r"(a3), "r"(b0), "r"(b1));
}

__device__ __forceinline__ void cp16(uint32_t dst, const void* src) {
    asm volatile("cp.async.ca.shared.global [%0], [%1], 16;" :: "r"(dst), "l"(src));
}

__device__ __forceinline__ void atomicMaxF(float* addr, float val) {
    int* ia = (int*)addr;
    int old = *ia;
    for (int it = 0; it < 1024 && __int_as_float(old) < val; it++) {
        int assumed = old;
        old = atomicCAS(ia, assumed, __float_as_int(val));
        if (old == assumed) break;
    }
}

// grid-wide barrier (co-residency checked at launch; bounded spin)
__device__ __forceinline__ void gsync() {
    __syncthreads();
    if (threadIdx.x == 0) {
        __threadfence();
        volatile unsigned* vgen = &g_bargen;
        unsigned gen = *vgen;
        if (atomicAdd(&g_barcnt, 1u) == gridDim.x - 1) {
            atomicExch(&g_barcnt, 0u);
            __threadfence();
            atomicAdd(&g_bargen, 1u);
        } else {
            long long spins = 0;
            while (*vgen == gen && spins < 10000000LL) { __nanosleep(32); spins++; }
            __threadfence();
        }
    }
    __syncthreads();
}

// ---------------- fused-epilogue tf32 GEMM tile: 64 rows x 128 cols --------------
// EPI 0: plain store (phase0)        EPI 1: chain stage1 + e1
// EPI 2: childsum fused stage1 + e1  EPI 3: chain stage2 + e2
// EPI 4: childsum stage2 + e2 (atomic scatter)
struct __align__(16) SmemG { float As[2][64][36]; float Bs[3][4608]; };

#define LOADB(chunkidx, buf) do {                                            \
    const char* _src = (const char*)(wtile + (size_t)(chunkidx) * 4608);     \
    uint32_t _d = bsa[(buf)];                                                \
    _Pragma("unroll")                                                        \
    for (int _off = 0; _off < 18432; _off += 4096) {                         \
        int _o = _off + tid * 16;                                            \
        if (_o < 18432) cp16(_d + _o, _src + _o);                            \
    }                                                                        \
    asm volatile("cp.async.commit_group;");                                  \
} while (0)

template<int EPI>
__device__ void gemm_fused(const float* __restrict__ A1,
                           const float* __restrict__ A2h,   // K>=512 half (nch=32); else pass A1
                           const int* __restrict__ arows,
                           const int* __restrict__ orows,
                           const float* __restrict__ wtile, // image base for this col-tile
                           const float* __restrict__ bias,  // col-tile-local bias (128)
                           int nch,                         // 16 or 32 chunks
                           float* __restrict__ out, int ldo,// EPI0 only
                           int n, int rt, int c0, SmemG* sm) {
    const int tid = threadIdx.x;
    const int lane = tid & 31, warp = tid >> 5;
    const int wr = warp >> 1, wc = warp & 1;          // 4x2 warp grid
    const int grp = lane >> 2, thr = lane & 3;
    const int r0 = rt * 64;

    const int la_r = tid >> 3;
    const int la_q = tid & 7;
    const int la_g = la_q >> 1, la_a = la_q & 1;
    const int ga0 = r0 + la_r, ga1 = r0 + la_r + 32;
    const bool v0 = ga0 < n, v1 = ga1 < n;
    const int nd0 = v0 ? (arows ? arows[ga0] : ga0) : 0;
    const int nd1 = v1 ? (arows ? arows[ga1] : ga1) : 0;
    const float* ap0  = A1  + (size_t)nd0 * 512;
    const float* ap0h = A2h + (size_t)nd0 * 512;
    const float* ap1  = A1  + (size_t)nd1 * 512;
    const float* ap1h = A2h + (size_t)nd1 * 512;

    uint32_t bsa[3];
    bsa[0] = (uint32_t)__cvta_generic_to_shared(&sm->Bs[0][0]);
    bsa[1] = (uint32_t)__cvta_generic_to_shared(&sm->Bs[1][0]);
    bsa[2] = (uint32_t)__cvta_generic_to_shared(&sm->Bs[2][0]);

    float c[8][4];
#pragma unroll
    for (int s = 0; s < 8; s++)
#pragma unroll
        for (int j = 0; j < 4; j++) c[s][j] = 0.f;

    // prologue: B0,B1 in flight; A0 stored; A1 in regs
    LOADB(0, 0);
    LOADB(1, 1);
    float4 x0 = v0 ? *(const float4*)(ap0 + la_q * 4) : make_float4(0, 0, 0, 0);
    float4 x1 = v1 ? *(const float4*)(ap1 + la_q * 4) : make_float4(0, 0, 0, 0);
    {
        float* d0 = &sm->As[0][la_r][la_g * 8 + la_a];
        d0[0] = to_tf32(x0.x); d0[2] = to_tf32(x0.y);
        d0[4] = to_tf32(x0.z); d0[6] = to_tf32(x0.w);
        float* d1 = &sm->As[0][la_r + 32][la_g * 8 + la_a];
        d1[0] = to_tf32(x1.x); d1[2] = to_tf32(x1.y);
        d1[4] = to_tf32(x1.z); d1[6] = to_tf32(x1.w);
    }
    x0 = v0 ? *(const float4*)(ap0 + 32 + la_q * 4) : make_float4(0, 0, 0, 0);
    x1 = v1 ? *(const float4*)(ap1 + 32 + la_q * 4) : make_float4(0, 0, 0, 0);

#pragma unroll 1
    for (int i = 0; i < nch; i++) {
        if (i == nch - 1) asm volatile("cp.async.wait_group 0;");
        else              asm volatile("cp.async.wait_group 1;");
        __syncthreads();

        if (i < nch - 1) {
            float* d0 = &sm->As[(i + 1) & 1][la_r][la_g * 8 + la_a];
            d0[0] = to_tf32(x0.x); d0[2] = to_tf32(x0.y);
            d0[4] = to_tf32(x0.z); d0[6] = to_tf32(x0.w);
            float* d1 = &sm->As[(i + 1) & 1][la_r + 32][la_g * 8 + la_a];
            d1[0] = to_tf32(x1.x); d1[2] = to_tf32(x1.y);
            d1[4] = to_tf32(x1.z); d1[6] = to_tf32(x1.w);
        }
        if (i < nch - 2) {
            int nc = i + 2;
            const float* pa0 = (nc < 16 ? ap0 : ap0h) + ((nc & 15) << 5);
            const float* pa1 = (nc < 16 ? ap1 : ap1h) + ((nc & 15) << 5);
            x0 = v0 ? *(const float4*)(pa0 + la_q * 4) : make_float4(0, 0, 0, 0);
            x1 = v1 ? *(const float4*)(pa1 + la_q * 4) : make_float4(0, 0, 0, 0);
            LOADB(nc, nc % 3);
        }

        const float* bcur = &sm->Bs[i % 3][0];
        const float(*acur)[36] = sm->As[i & 1];
#pragma unroll
        for (int st = 0; st < 4; st++) {
            const int kk = st * 8;
            float2 a02 = *(float2*)&acur[wr * 16 + grp][kk + 2 * thr];
            float2 a13 = *(float2*)&acur[wr * 16 + grp + 8][kk + 2 * thr];
            unsigned ua0 = __float_as_uint(a02.x), ua2 = __float_as_uint(a02.y);
            unsigned ua1 = __float_as_uint(a13.x), ua3 = __float_as_uint(a13.y);
#pragma unroll
            for (int s = 0; s < 8; s++) {
                float2 b = *(float2*)&bcur[(wc * 64 + s * 8 + grp) * 36 + kk + 2 * thr];
                mma8(c[s], ua0, ua1, ua2, ua3,
                     __float_as_uint(b.x), __float_as_uint(b.y));
            }
        }
    }
    __syncthreads();

    // ---- fused epilogues ----
    const int row_a = r0 + wr * 16 + grp;
    const int row_b = row_a + 8;
    const bool va = row_a < n, vb = row_b < n;
    const int oa = va ? (orows ? orows[row_a] : row_a) : 0;
    const int ob = vb ? (orows ? orows[row_b] : row_b) : 0;

#pragma unroll
    for (int s = 0; s < 8; s++) {
        const int lc = wc * 64 + s * 8 + 2 * thr;
        const int cc = c0 + lc;
        float2 bv = *(const float2*)(bias + lc);
        float va0 = c[s][0] + bv.x, va1 = c[s][1] + bv.y;
        float vb0 = c[s][2] + bv.x, vb1 = c[s][3] + bv.y;

        if (EPI == 0) {
            if (va) *(float2*)(out + (size_t)oa * ldo + cc) = make_float2(va0, va1);
            if (vb) *(float2*)(out + (size_t)ob * ldo + cc) = make_float2(vb0, vb1);
        } else if (EPI == 1) {
            // chain s1+e1: cols (i,o,f,z)/j; even pair=(i,o), odd pair=(f,z)
            const int j = cc >> 2;
            const bool evn = ((cc & 2) == 0);
            if (va) {
                const float* q = g_qx + (size_t)oa * 2560;
                if (evn) {
                    g_chig[(size_t)oa * 512 + j] = sigf(q[j] + va0);
                    g_chog[(size_t)oa * 512 + j] = sigf(q[512 + j] + va1);
                } else {
                    float fg = sigf(q[1024 + j] + va0);
                    float zg = sigf(q[1536 + j] + va1);
                    float pc = g_chc[(size_t)g_parent[oa] * 512 + j];
                    g_chs[(size_t)oa * 512 + j] = zg * tanhf(pc);
                    g_chfc[(size_t)oa * 512 + j] = fg * pc;
                }
            }
            if (vb) {
                const float* q = g_qx + (size_t)ob * 2560;
                if (evn) {
                    g_chig[(size_t)ob * 512 + j] = sigf(q[j] + vb0);
                    g_chog[(size_t)ob * 512 + j] = sigf(q[512 + j] + vb1);
                } else {
                    float fg = sigf(q[1024 + j] + vb0);
                    float zg = sigf(q[1536 + j] + vb1);
                    float pc = g_chc[(size_t)g_parent[ob] * 512 + j];
                    g_chs[(size_t)ob * 512 + j] = zg * tanhf(pc);
                    g_chfc[(size_t)ob * 512 + j] = fg * pc;
                }
            }
        } else if (EPI == 2) {
            // childsum fused s1+e1: cols (i,o,w,pad)/j; w lives on odd pair -> shfl
            const int j = cc >> 2;
            float wa = __shfl_xor_sync(0xffffffffu, va0, 1);
            float wb = __shfl_xor_sync(0xffffffffu, vb0, 1);
            const bool evn = ((cc & 2) == 0);
            if (evn) {
                if (va) {
                    const float* px = g_px + (size_t)oa * 2560;
                    float ig = sigf(px[j] + va0);
                    float og = sigf(px[1024 + j] + va1);
                    float u  = tanhf(px[2048 + j] + wa);
                    float c_ = ig * u + g_accfc[(size_t)oa * 512 + j];
                    g_csc[(size_t)oa * 512 + j] = c_;
                    g_csh[(size_t)oa * 512 + j] = og * tanhf(c_);
                }
                if (vb) {
                    const float* px = g_px + (size_t)ob * 2560;
                    float ig = sigf(px[j] + vb0);
                    float og = sigf(px[1024 + j] + vb1);
                    float u  = tanhf(px[2048 + j] + wb);
                    float c_ = ig * u + g_accfc[(size_t)ob * 512 + j];
                    g_csc[(size_t)ob * 512 + j] = c_;
                    g_csh[(size_t)ob * 512 + j] = og * tanhf(c_);
                }
            }
        } else if (EPI == 3) {
            // chain s2+e2: natural cols, per-col independent
            if (va) {
                const float* q = g_qx + (size_t)oa * 2560;
                float u0 = tanhf(q[2048 + cc] + va0);
                float c0_ = g_chig[(size_t)oa * 512 + cc] * u0 + g_chfc[(size_t)oa * 512 + cc];
                g_chc[(size_t)oa * 512 + cc] = c0_;
                g_chh[(size_t)oa * 512 + cc] = g_chog[(size_t)oa * 512 + cc] * tanhf(c0_);
                float u1 = tanhf(q[2048 + cc + 1] + va1);
                float c1_ = g_chig[(size_t)oa * 512 + cc + 1] * u1 + g_chfc[(size_t)oa * 512 + cc + 1];
                g_chc[(size_t)oa * 512 + cc + 1] = c1_;
                g_chh[(size_t)oa * 512 + cc + 1] = g_chog[(size_t)oa * 512 + cc + 1] * tanhf(c1_);
            }
            if (vb) {
                const float* q = g_qx + (size_t)ob * 2560;
                float u0 = tanhf(q[2048 + cc] + vb0);
                float c0_ = g_chig[(size_t)ob * 512 + cc] * u0 + g_chfc[(size_t)ob * 512 + cc];
                g_chc[(size_t)ob * 512 + cc] = c0_;
                g_chh[(size_t)ob * 512 + cc] = g_chog[(size_t)ob * 512 + cc] * tanhf(c0_);
                float u1 = tanhf(q[2048 + cc + 1] + vb1);
                float c1_ = g_chig[(size_t)ob * 512 + cc + 1] * u1 + g_chfc[(size_t)ob * 512 + cc + 1];
                g_chc[(size_t)ob * 512 + cc + 1] = c1_;
                g_chh[(size_t)ob * 512 + cc + 1] = g_chog[(size_t)ob * 512 + cc + 1] * tanhf(c1_);
            }
        } else if (EPI == 4) {
            // childsum s2+e2: cols (f,z)/j, atomic scatter to parent
            const int j = cc >> 1;
            if (va) {
                int p = g_parent[oa];
                float f = sigf(g_px[(size_t)p * 2560 + 512 + j] + va0);
                float z = sigf(g_px[(size_t)p * 2560 + 1536 + j] + va1);
                float c_ = g_csc[(size_t)oa * 512 + j];
                float h  = g_csh[(size_t)oa * 512 + j];
                atomicAdd(&g_acch[(size_t)p * 512 + j], h);
                atomicAdd(&g_accfc[(size_t)p * 512 + j], f * c_);
                atomicAdd(&g_acczc[(size_t)p * 512 + j], z * tanhf(c_));
            }
            if (vb) {
                int p = g_parent[ob];
                float f = sigf(g_px[(size_t)p * 2560 + 512 + j] + vb0);
                float z = sigf(g_px[(size_t)p * 2560 + 1536 + j] + vb1);
                float c_ = g_csc[(size_t)ob * 512 + j];
                float h  = g_csh[(size_t)ob * 512 + j];
                atomicAdd(&g_acch[(size_t)p * 512 + j], h);
                atomicAdd(&g_accfc[(size_t)p * 512 + j], f * c_);
                atomicAdd(&g_acczc[(size_t)p * 512 + j], z * tanhf(c_));
            }
        }
    }
}

// ---------------- setup kernels ----------------
__global__ __launch_bounds__(1024) void k_decode(const void* praw) {
    const int tid = threadIdx.x;
    __shared__ int s_is32;
    if (tid == 0) s_is32 = 0;
    __syncthreads();
    const int* w = (const int*)praw;
    for (int i = tid; i < Nn / 2; i += 1024)
        if (w[2 * i + 1] != 0) atomicOr(&s_is32, 1);
    __syncthreads();
    if (s_is32) {
        for (int i = tid; i < Nn; i += 1024) g_parent[i] = w[i];
    } else {
        const long long* l = (const long long*)praw;
        for (int i = tid; i < Nn; i += 1024) g_parent[i] = (int)l[i];
    }
}

__global__ void k_depth() {
    int idx = blockIdx.x * blockDim.x + threadIdx.x;
    int stride = gridDim.x * blockDim.x;
    for (int i = idx; i < Nn; i += stride) {
        int d = 0, j = i;
        for (int it = 0; it < Nn && j != 0; it++) {
            j = g_parent[j] & (Nn - 1);
            d++;
            if (j == 0) break;
        }
        g_depth[i] = d;
    }
}

__global__ __launch_bounds__(1024) void k_levels() {
    const int tid = threadIdx.x;
    __shared__ int s_maxd;
    if (tid == 0) s_maxd = 0;
    for (int d = tid; d < 256; d += 1024) g_lvlcnt[d] = 0;
    __syncthreads();
    int lm = 0;
    for (int i = tid; i < Nn; i += 1024) lm = max(lm, min(g_depth[i], 255));
    atomicMax(&s_maxd, lm);
    __syncthreads();
    if (tid == 0) g_maxdepth = s_maxd;
    for (int i = tid; i < Nn; i += 1024) atomicAdd(&g_lvlcnt[min(g_depth[i], 255)], 1);
    __syncthreads();
    if (tid == 0) {
        int s = 0;
        for (int d = 0; d < 255; d++) { g_lvlstart[d] = s; s += g_lvlcnt[d]; }
        g_lvlstart[255] = s;
    }
    __syncthreads();
    for (int d = tid; d < 256; d += 1024) g_lvlcnt[d] = 0;
    __syncthreads();
    for (int i = tid; i < Nn; i += 1024) {
        int d = min(g_depth[i], 255);
        int pos = atomicAdd(&g_lvlcnt[d], 1);
        g_order[g_lvlstart[d] + pos] = i;
    }
    __syncthreads();
    for (int p = tid; p < Nn; p += 1024) g_parorder[p] = g_parent[g_order[p]];
}

// ---------------- the persistent mega-kernel ----------------
__global__ __launch_bounds__(256, 2) void k_mega(
        const float* __restrict__ x,
        const float* __restrict__ csWx, const float* __restrict__ csbx,
        const float* __restrict__ csWio, const float* __restrict__ csbio,
        const float* __restrict__ csWfz, const float* __restrict__ csbfz,
        const float* __restrict__ csWum, const float* __restrict__ csbum,
        const float* __restrict__ chWx, const float* __restrict__ chbx,
        const float* __restrict__ chWh, const float* __restrict__ chbh,
        const float* __restrict__ chWum, const float* __restrict__ chbum,
        float* __restrict__ out) {
    extern __shared__ __align__(16) char smraw[];
    SmemG& sm = *(SmemG*)smraw;
    const int bid = blockIdx.x, nb = gridDim.x;
    const int tid = threadIdx.x;
    const int gidx = bid * 256 + tid, gstride = nb * 256;
    const int maxd = g_maxdepth;

    // ---- phase -1: zero accumulators, build biases + weight images ----
    {
        const size_t n1 = (size_t)(Nn + 1) * Mm;
        for (size_t i = gidx; i < n1; i += gstride) {
            g_acch[i] = 0.f; g_accfc[i] = 0.f; g_acczc[i] = 0.f;
        }
        if (gidx < 512) out[512 + gidx] = -1e30f;

        for (int i = gidx; i < 2048; i += gstride) {
            int j = i >> 2, gg = i & 3;
            g_bias_chwh[i] = chbh[gg * 512 + j];
            float bv;
            if (gg == 0) bv = csbio[j];
            else if (gg == 1) bv = csbio[512 + j];
            else if (gg == 2) bv = csbum[j];
            else bv = 0.f;
            g_bias_csiow[i] = bv;
        }
        for (int i = gidx; i < 1024; i += gstride) {
            int j = i >> 1, gg = i & 1;
            g_bias_csfz[i] = csbfz[gg * 512 + j];
        }

        const size_t total = (size_t)UNITS_TOTAL * 4608;
        for (size_t idx = gidx; idx < total; idx += gstride) {
            int unit = (int)(idx / 4608);
            int rem = (int)(idx % 4608);
            int row = rem / 36, pos = rem % 36;
            float v = 0.f;
            if (pos < 32) {
                int g = pos >> 3, q = pos & 7;
                int kk = g * 8 + (q & 1) * 4 + (q >> 1);
                int col, k, img;
                if (unit < 256)       { img = 0; int u = unit;        col = (u >> 4) * 128 + row; k = (u & 15) * 32 + kk; }
                else if (unit < 768)  { img = 1; int u = unit - 256;  col = (u >> 5) * 128 + row; k = (u & 31) * 32 + kk; }
                else if (unit < 832)  { img = 2; int u = unit - 768;  col = (u >> 4) * 128 + row; k = (u & 15) * 32 + kk; }
                else if (unit < 960)  { img = 3; int u = unit - 832;  col = (u >> 4) * 128 + row; k = (u & 15) * 32 + kk; }
                else if (unit < 1280) { img = 4; int u = unit - 960;  col = (u >> 4) * 128 + row; k = (u & 15) * 32 + kk; }
                else                  { img = 5; int u = unit - 1280; col = (u >> 4) * 128 + row; k = (u & 15) * 32 + kk; }
                if (img == 0) { int j = col >> 2, gg = col & 3; v = chWh[(size_t)(gg * 512 + j) * 512 + k]; }
                else if (img == 1) {
                    int j = col >> 2, gg = col & 3;
                    if (gg == 0)      v = (k < 512) ? csWio[(size_t)j * 512 + k] : 0.f;
                    else if (gg == 1) v = (k < 512) ? csWio[(size_t)(512 + j) * 512 + k] : 0.f;
                    else if (gg == 2) v = (k >= 512) ? csWum[(size_t)j * 512 + (k - 512)] : 0.f;
                    else v = 0.f;
                }
                else if (img == 2) v = chWum[(size_t)col * 512 + k];
                else if (img == 3) { int j = col >> 1, gg = col & 1; v = csWfz[(size_t)(gg * 512 + j) * 512 + k]; }
                else if (img == 4) v = csWx[(size_t)col * 512 + k];
                else               v = chWx[(size_t)col * 512 + k];
                v = to_tf32(v);
            }
            g_wt[idx] = v;
        }
    }
    gsync();

    // ---- phase 0: big input GEMMs (plain epilogue) ----
    for (int tile = bid; tile < 5120; tile += nb) {
        int rt = tile & 127, ct = tile >> 7;          // 128 row-tiles x 40 col-tiles
        if (ct < 20)
            gemm_fused<0>(x, x, nullptr, nullptr,
                          g_wt + (size_t)(UB_CSWX + ct * 16) * 4608, csbx + ct * 128,
                          16, g_px, 2560, Nn, rt, ct * 128, &sm);
        else
            gemm_fused<0>(x, x, nullptr, nullptr,
                          g_wt + (size_t)(UB_CHWX + (ct - 20) * 16) * 4608, chbx + (ct - 20) * 128,
                          16, g_qx, 2560, Nn, rt, (ct - 20) * 128, &sm);
    }
    gsync();

    // ---- superstep loop: chain level t  +  childsum level (maxd - t) ----
    for (int t = 0; t <= maxd; t++) {
        const int s_ch = g_lvlstart[t];
        const int n_ch = g_lvlstart[t + 1] - s_ch;
        const int d = maxd - t;
        const int s_cs = g_lvlstart[d];
        const int n_cs = g_lvlstart[d + 1] - s_cs;
        const int rt_ch = (n_ch + 63) >> 6;
        const int rt_cs = (n_cs + 63) >> 6;

        // phase A: chain s1+e1 (16 tiles/rowgrp) + childsum fused s1+e1 (16 tiles, K=1024)
        {
            const int tch = rt_ch * 16, tcs = rt_cs * 16;
            for (int i = bid; i < tch + tcs; i += nb) {
                if (i < tch) {
                    int rt = i >> 4, ct = i & 15;
                    gemm_fused<1>(g_chh, g_chh, g_parorder + s_ch, g_order + s_ch,
                                  g_wt + (size_t)(UB_CHWH + ct * 16) * 4608,
                                  g_bias_chwh + ct * 128,
                                  16, nullptr, 0, n_ch, rt, ct * 128, &sm);
                } else {
                    int k = i - tch, rt = k >> 4, ct = k & 15;
                    gemm_fused<2>(g_acch, g_acczc, g_order + s_cs, g_order + s_cs,
                                  g_wt + (size_t)(UB_CSIOW + ct * 32) * 4608,
                                  g_bias_csiow + ct * 128,
                                  32, nullptr, 0, n_cs, rt, ct * 128, &sm);
                }
            }
        }
        gsync();

        // phase B: chain s2+e2 (4 tiles) + childsum s2+e2 (8 tiles)
        {
            const int tch = rt_ch * 4, tcs = rt_cs * 8;
            for (int i = bid; i < tch + tcs; i += nb) {
                if (i < tch) {
                    int rt = i >> 2, ct = i & 3;
                    gemm_fused<3>(g_chs, g_chs, g_order + s_ch, g_order + s_ch,
                                  g_wt + (size_t)(UB_CHWUM + ct * 16) * 4608,
                                  chbum + ct * 128,
                                  16, nullptr, 0, n_ch, rt, ct * 128, &sm);
                } else {
                    int k = i - tch, rt = k >> 3, ct = k & 7;
                    gemm_fused<4>(g_csh, g_csh, g_order + s_cs, g_order + s_cs,
                                  g_wt + (size_t)(UB_CSFZ + ct * 16) * 4608,
                                  g_bias_csfz + ct * 128,
                                  16, nullptr, 0, n_cs, rt, ct * 128, &sm);
                }
            }
        }
        gsync();
    }

    // ---- final: frep = h_root (node 0), brep = colmax(chain h) ----
    if (bid < 32) {
        float m0 = -1e30f, m1 = -1e30f;
        const int r0 = bid * 256, r1 = r0 + 256;
        for (int r = r0; r < r1; r++) {
            m0 = fmaxf(m0, g_chh[(size_t)r * Mm + tid]);
            m1 = fmaxf(m1, g_chh[(size_t)r * Mm + 256 + tid]);
        }
        atomicMaxF(out + 512 + tid, m0);
        atomicMaxF(out + 768 + tid, m1);
    } else if (bid == 32) {
        out[tid] = g_csh[tid];
        out[256 + tid] = g_csh[256 + tid];
    }
}

// ---------------- launch ----------------
extern "C" void kernel_launch(void* const* d_in, const int* in_sizes, int n_in,
                              void* d_out, int out_size) {
    const float* inputs = (const float*)d_in[0];
    const void* parent = d_in[1];
    const float* csWx = (const float*)d_in[2];
    const float* csbx = (const float*)d_in[3];
    const float* csWio = (const float*)d_in[4];
    const float* csbio = (const float*)d_in[5];
    const float* csWfz = (const float*)d_in[6];
    const float* csbfz = (const float*)d_in[7];
    const float* csWum = (const float*)d_in[8];
    const float* csbum = (const float*)d_in[9];
    const float* chWx = (const float*)d_in[10];
    const float* chbx = (const float*)d_in[11];
    const float* chWh = (const float*)d_in[12];
    const float* chbh = (const float*)d_in[13];
    const float* chWum = (const float*)d_in[14];
    const float* chbum = (const float*)d_in[15];
    float* out = (float*)d_out;

    const int smbytes = (int)sizeof(SmemG);   // 73728
    cudaFuncSetAttribute(k_mega, cudaFuncAttributeMaxDynamicSharedMemorySize, smbytes);

    int occ = 1;
    cudaOccupancyMaxActiveBlocksPerMultiprocessor(&occ, k_mega, 256, smbytes);
    if (occ < 1) occ = 1;
    int smcount = 148;
    cudaDeviceGetAttribute(&smcount, cudaDevAttrMultiProcessorCount, 0);
    int nb = smcount * (occ < 2 ? occ : 2);
    if (nb < 33) nb = 33;

    k_decode<<<1, 1024>>>(parent);
    k_depth<<<64, 256>>>();
    k_levels<<<1, 1024>>>();
    k_mega<<<nb, 256, smbytes>>>(inputs, csWx, csbx, csWio, csbio, csWfz, csbfz,
                                 csWum, csbum, chWx, chbx, chWh, chbh, chWum, chbum, out);
}